// round 17
// baseline (speedup 1.0000x reference)
#include <cuda_runtime.h>
#include <cuda_fp16.h>
#include <cstdint>
#include <math.h>

#define S_LEN    4096
#define D_MODEL  1024
#define QKV_COLS 3072
#define N_HEADS  16
#define HEAD_DIM 64
#define ATT_SCALE 0.125f

// ---------------- scratch (__device__ globals; no cudaMalloc) ----------------
static __device__ __align__(256) __half g_xh[S_LEN * D_MODEL];
static __device__ __align__(256) __half g_qkv[S_LEN * QKV_COLS];   // fp16 qkv
static __device__ __align__(256) __half g_ah[S_LEN * D_MODEL];
static __device__ __align__(256) __half g_wqh[QKV_COLS * D_MODEL]; // [N][K] fp16
static __device__ __align__(256) __half g_woh[D_MODEL * D_MODEL];

// ---------------- PTX helpers ----------------
__device__ __forceinline__ uint32_t smem_u32(const void* p) {
    uint32_t a;
    asm("{ .reg .u64 t; cvta.to.shared.u64 t, %1; cvt.u32.u64 %0, t; }"
        : "=r"(a) : "l"(p));
    return a;
}
__device__ __forceinline__ void cp_async16(uint32_t saddr, const void* gptr) {
    asm volatile("cp.async.cg.shared.global [%0], [%1], 16;"
                 :: "r"(saddr), "l"(gptr));
}
#define CP_COMMIT() asm volatile("cp.async.commit_group;" ::: "memory")
#define CP_WAIT(n)  asm volatile("cp.async.wait_group %0;" :: "n"(n) : "memory")

__device__ __forceinline__ void ldsm_x4(uint32_t* r, uint32_t addr) {
    asm volatile("ldmatrix.sync.aligned.m8n8.x4.shared.b16 {%0,%1,%2,%3}, [%4];"
                 : "=r"(r[0]), "=r"(r[1]), "=r"(r[2]), "=r"(r[3]) : "r"(addr));
}
__device__ __forceinline__ void ldsm_x4_t(uint32_t* r, uint32_t addr) {
    asm volatile("ldmatrix.sync.aligned.m8n8.x4.trans.shared.b16 {%0,%1,%2,%3}, [%4];"
                 : "=r"(r[0]), "=r"(r[1]), "=r"(r[2]), "=r"(r[3]) : "r"(addr));
}
__device__ __forceinline__ void mma_f16(float* c, const uint32_t* a, const uint32_t* b) {
    asm volatile("mma.sync.aligned.m16n8k16.row.col.f32.f16.f16.f32 "
                 "{%0,%1,%2,%3}, {%4,%5,%6,%7}, {%8,%9}, {%0,%1,%2,%3};"
                 : "+f"(c[0]), "+f"(c[1]), "+f"(c[2]), "+f"(c[3])
                 : "r"(a[0]), "r"(a[1]), "r"(a[2]), "r"(a[3]), "r"(b[0]), "r"(b[1]));
}
__device__ __forceinline__ uint32_t pack_h(float x, float y) {
    __half hx = __float2half_rn(x), hy = __float2half_rn(y);
    return ((uint32_t)__half_as_ushort(hy) << 16) | __half_as_ushort(hx);
}

// ---------------- convert kernels ----------------
__global__ void round_rows_kernel(const float* __restrict__ src,
                                  __half* __restrict__ hi, int n)
{
    int i = (blockIdx.x * blockDim.x + threadIdx.x) * 4;
    if (i >= n) return;
    float4 v = *(const float4*)(src + i);
    uint32_t h0 = pack_h(v.x, v.y);
    uint32_t h1 = pack_h(v.z, v.w);
    *(uint2*)(hi + i) = make_uint2(h0, h1);
}

__global__ void transpose_round_kernel(const float* __restrict__ w,
                                       __half* __restrict__ hi,
                                       int K, int N)
{
    __shared__ float tile[32][33];
    const int n0 = blockIdx.x * 32, k0 = blockIdx.y * 32;
    const int tx = threadIdx.x, ty = threadIdx.y;   // 32 x 8
#pragma unroll
    for (int i = 0; i < 4; i++)
        tile[ty + 8 * i][tx] = w[(size_t)(k0 + ty + 8 * i) * N + n0 + tx];
    __syncthreads();
#pragma unroll
    for (int i = 0; i < 4; i++) {
        const int r = ty + 8 * i;
        hi[(size_t)(n0 + r) * K + k0 + tx] = __float2half_rn(tile[tx][r]);
    }
}

// ---- raw mma.sync fp16 1-pass GEMM: C = Ah·Bh^T + bias, 3-stage cp.async ---
// hilo: 0 = fp32 out, 2 = fp16 (rounded) out
#define GLD 40
#define GTILE  (128 * GLD * 2)            // 10240 B per array
#define GSTAGE (2 * GTILE)                // 20480 B per stage (Ah, Bh)
#define GNSTG  3                          // 3 stages = 61440 B (aliased by epilogue)
#define GEMM_SMEM (128 * 132 * 4)         // 67584 B

__global__ __launch_bounds__(256, 2)      // force <=128 regs -> 2 CTAs/SM
void gemm_mma_kernel(const __half* __restrict__ Ah,
                     const __half* __restrict__ Bh,
                     const float* __restrict__ bias,
                     float* __restrict__ Cf,
                     __half* __restrict__ Ch,
                     int hilo, int M, int N, int K)
{
    extern __shared__ char smraw[];
    float* Cs = (float*)smraw;
    const uint32_t sb = smem_u32(smraw);

    const int tid = threadIdx.x;
    const int wid = tid >> 5;
    const int lane = tid & 31;
    const int wr = wid >> 1;
    const int wc = wid & 1;
    const int g  = lane >> 2;
    const int t  = lane & 3;
    const int lr = lane & 15;
    const int lc8 = (lane >> 4) * 8;
    const int kk = (lane & 7) + ((lane & 16) >> 1);
    const int kd8 = lane & 8;
    const int m0 = blockIdx.y * 128, n0 = blockIdx.x * 128;

    float acc[16][4];
#pragma unroll
    for (int q = 0; q < 16; q++)
#pragma unroll
        for (int e = 0; e < 4; e++) acc[q][e] = 0.f;

    int crow[2], cbyte[2];
#pragma unroll
    for (int i = 0; i < 2; i++) {
        const int idx = tid + i * 256;
        crow[i]  = idx >> 2;
        cbyte[i] = (idx & 3) * 16;
    }

    const int NT = K / 32;

    // prefetch stages 0 and 1
#pragma unroll
    for (int s = 0; s < 2; s++) {
        const int kx = s * 32;
        const uint32_t st = sb + s * GSTAGE;
#pragma unroll
        for (int i = 0; i < 2; i++) {
            const int r = crow[i];
            const int gcol = kx + cbyte[i] / 2;
            const uint32_t so = (uint32_t)(r * GLD * 2 + cbyte[i]);
            cp_async16(st + so,         Ah + (size_t)(m0 + r) * K + gcol);
            cp_async16(st + GTILE + so, Bh + (size_t)(n0 + r) * K + gcol);
        }
        CP_COMMIT();
    }

    for (int kt = 0; kt < NT; kt++) {
        __syncthreads();   // consumers of stage kt-1 done -> its buffer free
        if (kt + 2 < NT) {
            const int k1 = (kt + 2) * 32;
            const uint32_t st = sb + ((kt + 2) % GNSTG) * GSTAGE;
#pragma unroll
            for (int i = 0; i < 2; i++) {
                const int r = crow[i];
                const int gcol = k1 + cbyte[i] / 2;
                const uint32_t so = (uint32_t)(r * GLD * 2 + cbyte[i]);
                cp_async16(st + so,         Ah + (size_t)(m0 + r) * K + gcol);
                cp_async16(st + GTILE + so, Bh + (size_t)(n0 + r) * K + gcol);
            }
            CP_COMMIT();
            CP_WAIT(2);
        } else if (kt + 1 < NT) {
            CP_WAIT(1);
        } else {
            CP_WAIT(0);
        }
        __syncthreads();   // stage kt visible

        const uint32_t uAh = sb + (kt % GNSTG) * GSTAGE;
        const uint32_t uBh = uAh + GTILE;

#pragma unroll
        for (int sub = 0; sub < 2; sub++) {
            const int kc = sub * 16;
            uint32_t ah[2][4];
#pragma unroll
            for (int i = 0; i < 2; i++) {
                const uint32_t aoff =
                    (uint32_t)(((wr * 32 + i * 16 + lr) * GLD + kc + lc8) * 2);
                ldsm_x4(ah[i], uAh + aoff);
            }
#pragma unroll
            for (int jj = 0; jj < 4; jj++) {
                uint32_t bh[4];
                const uint32_t boff =
                    (uint32_t)(((wc * 64 + jj * 16 + kk) * GLD + kc + kd8) * 2);
                ldsm_x4(bh, uBh + boff);
#pragma unroll
                for (int i = 0; i < 2; i++) {
                    mma_f16(acc[i * 8 + 2 * jj],     ah[i], bh);
                    mma_f16(acc[i * 8 + 2 * jj + 1], ah[i], bh + 2);
                }
            }
        }
    }

    __syncthreads();
#pragma unroll
    for (int i = 0; i < 2; i++)
#pragma unroll
        for (int f = 0; f < 8; f++) {
            const int row = wr * 32 + i * 16 + g;
            const int col = wc * 64 + 8 * f + 2 * t;
            const float* c = acc[i * 8 + f];
            *(float2*)&Cs[row * 132 + col]       = make_float2(c[0], c[1]);
            *(float2*)&Cs[(row + 8) * 132 + col] = make_float2(c[2], c[3]);
        }
    __syncthreads();

    {
        const int r = tid >> 1;
        const int cb = (tid & 1) * 64;
        const float* bp = bias + n0 + cb;
        const float* sp = &Cs[r * 132 + cb];
        if (hilo == 0) {
            float* cp = Cf + (size_t)(m0 + r) * N + n0 + cb;
#pragma unroll
            for (int j = 0; j < 64; j += 4) {
                float4 o;
                o.x = sp[j+0] + bp[j+0]; o.y = sp[j+1] + bp[j+1];
                o.z = sp[j+2] + bp[j+2]; o.w = sp[j+3] + bp[j+3];
                *(float4*)(cp + j) = o;
            }
        } else {
            __half* hp = Ch + (size_t)(m0 + r) * N + n0 + cb;
#pragma unroll
            for (int j = 0; j < 64; j += 4) {
                uint32_t h0 = pack_h(sp[j+0] + bp[j+0], sp[j+1] + bp[j+1]);
                uint32_t h1 = pack_h(sp[j+2] + bp[j+2], sp[j+3] + bp[j+3]);
                *(uint2*)(hp + j) = make_uint2(h0, h1);
            }
        }
    }
}

// ---------------------------------------------------------------------------
// Flash attention fp16, 1-pass QK and PV; output rounded fp16. 2 CTAs/SM.
// P packed to fp16 frags in one hoisted pass (sfr dies before PV loop).
// ---------------------------------------------------------------------------
#define ALD 72                              // fp16 elems per smem row
#define FARR (128 * ALD * 2)                // 18432 B per array
#define FA_KVSTAGE (2 * FARR)               // Kh Vh = 36864 B
#define FA_KVBASE  FARR                     // after Qh
#define FA_SMEM (FA_KVBASE + 2 * FA_KVSTAGE)  // 92160 B

__global__ __launch_bounds__(256, 2)
void flash_attn_mma_kernel(const __half* __restrict__ qkv,
                           __half* __restrict__ oh)
{
    extern __shared__ char smraw[];
    __half* sQh = (__half*)smraw;
    const uint32_t sb = smem_u32(smraw);

    const int qb  = gridDim.x - 1 - blockIdx.x;   // long rows first
    const int h   = blockIdx.y;
    const int tid = threadIdx.x;
    const int wid = tid >> 5;
    const int lane = tid & 31;
    const int q0  = qb * 128;

    const int g  = lane >> 2;
    const int t  = lane & 3;
    const int lr = lane & 15;
    const int lc8 = (lane >> 4) * 8;
    const int kk = (lane & 7) + ((lane & 16) >> 1);
    const int kd8 = lane & 8;

    const int colK = D_MODEL + h * HEAD_DIM;
    const int colV = 2 * D_MODEL + h * HEAD_DIM;

    int crow[4], cbyte[4];
#pragma unroll
    for (int i = 0; i < 4; i++) {
        const int idx = tid + i * 256;
        crow[i]  = idx >> 3;
        cbyte[i] = (idx & 7) * 16;
    }

    // ---- load Q tile ----
#pragma unroll
    for (int i = 0; i < 4; i++) {
        const int r = crow[i], c = cbyte[i] / 2;
        const size_t gofs = (size_t)(q0 + r) * QKV_COLS + h * HEAD_DIM + c;
        *(uint4*)(sQh + r * ALD + c) = *(const uint4*)(qkv + gofs);
    }

    // ---- prefetch K/V stage 0 ----
    {
        const uint32_t st = sb + FA_KVBASE;
#pragma unroll
        for (int i = 0; i < 4; i++) {
            const int r = crow[i];
            const uint32_t so = (uint32_t)(r * ALD * 2 + cbyte[i]);
            const size_t gr = (size_t)r * QKV_COLS;
            const int c = cbyte[i] / 2;
            cp_async16(st + so,        qkv + gr + colK + c);
            cp_async16(st + FARR + so, qkv + gr + colV + c);
        }
        CP_COMMIT();
    }

    float ofr[8][4];
    float m0 = -1e30f, m1 = -1e30f, l0 = 0.f, l1 = 0.f;
#pragma unroll
    for (int j = 0; j < 8; j++)
#pragma unroll
        for (int e = 0; e < 4; e++) ofr[j][e] = 0.f;

    for (int kt = 0; kt <= qb; kt++) {
        __syncthreads();
        if (kt + 1 <= qb) {
            const int k1 = (kt + 1) * 128;
            const uint32_t st = sb + FA_KVBASE + ((kt + 1) & 1) * FA_KVSTAGE;
#pragma unroll
            for (int i = 0; i < 4; i++) {
                const int r = crow[i];
                const uint32_t so = (uint32_t)(r * ALD * 2 + cbyte[i]);
                const size_t gr = (size_t)(k1 + r) * QKV_COLS;
                const int c = cbyte[i] / 2;
                cp_async16(st + so,        qkv + gr + colK + c);
                cp_async16(st + FARR + so, qkv + gr + colV + c);
            }
            CP_COMMIT();
            CP_WAIT(1);
        } else {
            CP_WAIT(0);
        }
        __syncthreads();

        const uint32_t stg = sb + FA_KVBASE + (kt & 1) * FA_KVSTAGE;
        const uint32_t uKh = stg, uVh = stg + FARR;
        const uint32_t uQh = sb;

        // ---- S = Qh·Kh^T ----
        float sfr[16][4];
#pragma unroll
        for (int j = 0; j < 16; j++)
#pragma unroll
            for (int e = 0; e < 4; e++) sfr[j][e] = 0.f;

#pragma unroll
        for (int u = 0; u < 4; u++) {
            uint32_t aQh[4];
            const uint32_t qoff =
                (uint32_t)(((wid * 16 + lr) * ALD + 16 * u + lc8) * 2);
            ldsm_x4(aQh, uQh + qoff);
#pragma unroll
            for (int jj = 0; jj < 8; jj++) {
                uint32_t bKh[4];
                const uint32_t koff =
                    (uint32_t)(((16 * jj + kk) * ALD + 16 * u + kd8) * 2);
                ldsm_x4(bKh, uKh + koff);
                mma_f16(sfr[2*jj],   aQh, bKh);
                mma_f16(sfr[2*jj+1], aQh, bKh + 2);
            }
        }

        // ---- scale + causal mask ----
        if (kt == qb) {
            const int gq0 = wid * 16 + g, gq1 = gq0 + 8;
#pragma unroll
            for (int j = 0; j < 16; j++) {
                const int c = 8 * j + 2 * t;
                sfr[j][0] = (c     <= gq0) ? sfr[j][0] * ATT_SCALE : -1e30f;
                sfr[j][1] = (c + 1 <= gq0) ? sfr[j][1] * ATT_SCALE : -1e30f;
                sfr[j][2] = (c     <= gq1) ? sfr[j][2] * ATT_SCALE : -1e30f;
                sfr[j][3] = (c + 1 <= gq1) ? sfr[j][3] * ATT_SCALE : -1e30f;
            }
        } else {
#pragma unroll
            for (int j = 0; j < 16; j++) {
                sfr[j][0] *= ATT_SCALE; sfr[j][1] *= ATT_SCALE;
                sfr[j][2] *= ATT_SCALE; sfr[j][3] *= ATT_SCALE;
            }
        }

        // ---- online softmax ----
        float mn0 = m0, mn1 = m1;
#pragma unroll
        for (int j = 0; j < 16; j++) {
            mn0 = fmaxf(mn0, fmaxf(sfr[j][0], sfr[j][1]));
            mn1 = fmaxf(mn1, fmaxf(sfr[j][2], sfr[j][3]));
        }
        mn0 = fmaxf(mn0, __shfl_xor_sync(0xffffffffu, mn0, 1));
        mn0 = fmaxf(mn0, __shfl_xor_sync(0xffffffffu, mn0, 2));
        mn1 = fmaxf(mn1, __shfl_xor_sync(0xffffffffu, mn1, 1));
        mn1 = fmaxf(mn1, __shfl_xor_sync(0xffffffffu, mn1, 2));

        const float alpha0 = __expf(m0 - mn0);
        const float alpha1 = __expf(m1 - mn1);
        m0 = mn0; m1 = mn1;

        float sum0 = 0.f, sum1 = 0.f;
#pragma unroll
        for (int j = 0; j < 16; j++) {
            sfr[j][0] = __expf(sfr[j][0] - mn0);
            sfr[j][1] = __expf(sfr[j][1] - mn0);
            sfr[j][2] = __expf(sfr[j][2] - mn1);
            sfr[j][3] = __expf(sfr[j][3] - mn1);
            sum0 += sfr[j][0] + sfr[j][1];
            sum1 += sfr[j][2] + sfr[j][3];
        }
        sum0 += __shfl_xor_sync(0xffffffffu, sum0, 1);
        sum0 += __shfl_xor_sync(0xffffffffu, sum0, 2);
        sum1 += __shfl_xor_sync(0xffffffffu, sum1, 1);
        sum1 += __shfl_xor_sync(0xffffffffu, sum1, 2);
        l0 = l0 * alpha0 + sum0;
        l1 = l1 * alpha1 + sum1;

#pragma unroll
        for (int j = 0; j < 8; j++) {
            ofr[j][0] *= alpha0; ofr[j][1] *= alpha0;
            ofr[j][2] *= alpha1; ofr[j][3] *= alpha1;
        }

        // ---- hoisted P pack: sfr -> aP (sfr dead afterwards) ----
        uint32_t aP[8][4];
#pragma unroll
        for (int u = 0; u < 8; u++) {
            aP[u][0] = pack_h(sfr[2*u][0],   sfr[2*u][1]);
            aP[u][1] = pack_h(sfr[2*u][2],   sfr[2*u][3]);
            aP[u][2] = pack_h(sfr[2*u+1][0], sfr[2*u+1][1]);
            aP[u][3] = pack_h(sfr[2*u+1][2], sfr[2*u+1][3]);
        }

        // ---- O += Ph·Vh (pure ldsm+mma stream) ----
#pragma unroll
        for (int u = 0; u < 8; u++) {
#pragma unroll
            for (int cc = 0; cc < 4; cc++) {
                uint32_t bVh[4];
                const uint32_t voff =
                    (uint32_t)(((16 * u + lr) * ALD + 16 * cc + lc8) * 2);
                ldsm_x4_t(bVh, uVh + voff);
                mma_f16(ofr[2*cc],     aP[u], bVh);
                mma_f16(ofr[2*cc + 1], aP[u], bVh + 2);
            }
        }
    }

    // ---- epilogue: normalize, round fp16, store ----
    const float inv0 = 1.f / l0, inv1 = 1.f / l1;
    const int row0 = q0 + wid * 16 + g, row1 = row0 + 8;
#pragma unroll
    for (int j = 0; j < 8; j++) {
        const int c = h * HEAD_DIM + 8 * j + 2 * t;
        *(uint32_t*)(oh + (size_t)row0 * D_MODEL + c) =
            pack_h(ofr[j][0] * inv0, ofr[j][1] * inv0);
        *(uint32_t*)(oh + (size_t)row1 * D_MODEL + c) =
            pack_h(ofr[j][2] * inv1, ofr[j][3] * inv1);
    }
}

// ---------------------------------------------------------------------------
extern "C" void kernel_launch(void* const* d_in, const int* in_sizes, int n_in,
                              void* d_out, int out_size)
{
    const float* x     = (const float*)d_in[0];
    const float* w_qkv = (const float*)d_in[1];
    const float* b_qkv = (const float*)d_in[2];
    const float* w_out = (const float*)d_in[3];
    const float* b_out = (const float*)d_in[4];
    float* out = (float*)d_out;

    __half *xh, *qkv, *ah, *wqh, *woh;
    cudaGetSymbolAddress((void**)&xh, g_xh);
    cudaGetSymbolAddress((void**)&qkv, g_qkv);
    cudaGetSymbolAddress((void**)&ah, g_ah);
    cudaGetSymbolAddress((void**)&wqh, g_wqh);
    cudaGetSymbolAddress((void**)&woh, g_woh);

    cudaFuncSetAttribute(gemm_mma_kernel,
                         cudaFuncAttributeMaxDynamicSharedMemorySize, GEMM_SMEM);
    cudaFuncSetAttribute(flash_attn_mma_kernel,
                         cudaFuncAttributeMaxDynamicSharedMemorySize, FA_SMEM);

    {
        const int nx = S_LEN * D_MODEL;
        round_rows_kernel<<<nx / (256 * 4), 256>>>(x, xh, nx);
        dim3 g1(QKV_COLS / 32, D_MODEL / 32), b1(32, 8);
        transpose_round_kernel<<<g1, b1>>>(w_qkv, wqh, D_MODEL, QKV_COLS);
        dim3 g2(D_MODEL / 32, D_MODEL / 32);
        transpose_round_kernel<<<g2, b1>>>(w_out, woh, D_MODEL, D_MODEL);
    }

    // 1) qkv (fp16) = xh @ wqh + b_qkv   (1-pass)
    {
        dim3 grid(QKV_COLS / 128, S_LEN / 128);
        gemm_mma_kernel<<<grid, 256, GEMM_SMEM>>>(xh, wqh, b_qkv,
                                                  nullptr, qkv, 2,
                                                  S_LEN, QKV_COLS, D_MODEL);
    }
    // 2) attention -> ah (fp16, rounded)
    {
        dim3 grid(S_LEN / 128, N_HEADS);
        flash_attn_mma_kernel<<<grid, 256, FA_SMEM>>>(qkv, ah);
    }
    // 3) out = ah @ woh + b_out (fp32, 1-pass)
    {
        dim3 grid(D_MODEL / 128, S_LEN / 128);
        gemm_mma_kernel<<<grid, 256, GEMM_SMEM>>>(ah, woh, b_out,
                                                  out, nullptr, 0,
                                                  S_LEN, D_MODEL, D_MODEL);
    }
}